// round 14
// baseline (speedup 1.0000x reference)
#include <cuda_runtime.h>
#include <cuda_bf16.h>

#define DT_F      0.01f
#define DT_D      0.01
#define REG_W     0.01
#define EPS_L     1e-6f
#define LN_MINVAR (-4.6051702f)   // ln(0.01)
#define BATCH     256
#define TLEN      16384
#define NTHR      256             // threads per CTA (8 warps)
#define NWARP     8
#define NCHUNK    8               // chunks per CTA
#define CHUNK_TS  (NTHR*2)        // 512 timesteps per chunk (2 ts per thread)
#define SEG       (NCHUNK*CHUNK_TS) // 4096 timesteps per CTA segment
#define NSEG      (TLEN/SEG)      // 4 segments per row
#define NGRID     (BATCH*NSEG)    // 1024 CTAs
#define NREC      (BATCH*NSEG)    // 1024 records

// Per-segment records, [seg][row] so pass-2 reads coalesced.
// recA = (sum_vel.x, sum_vel.y, sum_a.x, sum_a.y)
// recB = (sum_a2, lve, lcs, rgs)
__device__ float4 g_recA[NREC];
__device__ float4 g_recB[NREC];

// ================= pass 1: streaming workers, NO fences/atomics =================
__global__ __launch_bounds__(NTHR)
void mtl_pass1_kernel(const float4* __restrict__ vel4,
                      const float4* __restrict__ cov4,
                      const float4* __restrict__ vgt4,
                      const float4* __restrict__ pgt4,
                      const float2* __restrict__ vel2)
{
    __shared__ float2 wsum[NWARP];        // raw warp totals
    __shared__ float2 wpre[NWARP];        // inclusive-scanned warp totals
    __shared__ float  sred[NWARP][6];

    const int tid  = threadIdx.x;
    const int lane = tid & 31;
    const int wid  = tid >> 5;
    const int row  = blockIdx.x & (BATCH - 1);
    const int q    = blockIdx.x >> 8;     // segment 0..3

    const int base_f4 = (row * TLEN + q * SEG) >> 1;   // float4 index of segment start

    const float2 v0  = vel2[row * TLEN];  // broadcast
    const float dv0x = DT_F * v0.x;
    const float dv0y = DT_F * v0.y;

    float carx = 0.f, cary = 0.f;         // segment-local prefix carry
    float sax = 0.f, say = 0.f, sa2 = 0.f;
    float lve = 0.f, lcs = 0.f, rgs = 0.f;

    #pragma unroll 1
    for (int ch = 0; ch < NCHUNK; ++ch) {
        const int f4 = base_f4 + (ch * CHUNK_TS >> 1) + tid;

        const float4 v  = vel4[f4];
        const float4 c4 = cov4[f4];
        const float4 g  = vgt4[f4];
        const float4 p  = pgt4[f4];

        // ---- warp scan of per-thread (2 ts) vel sums ----
        const float tsx = v.x + v.z;
        const float tsy = v.y + v.w;
        float ix = tsx, iy = tsy;
        #pragma unroll
        for (int off = 1; off < 32; off <<= 1) {
            const float nx = __shfl_up_sync(0xffffffffu, ix, off);
            const float ny = __shfl_up_sync(0xffffffffu, iy, off);
            if (lane >= off) { ix += nx; iy += ny; }
        }
        if (lane == 31) wsum[wid] = make_float2(ix, iy);
        __syncthreads();                  // barrier 1: wsum visible

        // warp 0 lanes 0..7 scan the 8 warp totals into wpre
        if (tid < NWARP) {
            float sx = wsum[tid].x, sy = wsum[tid].y;
            #pragma unroll
            for (int off = 1; off < NWARP; off <<= 1) {
                const float nx = __shfl_up_sync(0xffu, sx, off);
                const float ny = __shfl_up_sync(0xffu, sy, off);
                if (tid >= off) { sx += nx; sy += ny; }
            }
            wpre[tid] = make_float2(sx, sy);
        }
        __syncthreads();                  // barrier 2: wpre visible
        // Hazard note: next chunk's writes to wsum happen only after all warps
        // pass this barrier (readers of wsum finished before it); wpre reads
        // below complete before any warp reaches next chunk's barrier 1, which
        // gates the next wpre writes. Two barriers suffice, no double buffer.

        float ex = carx + (ix - tsx);
        float ey = cary + (iy - tsy);
        if (wid > 0) { ex += wpre[wid - 1].x; ey += wpre[wid - 1].y; }
        carx += wpre[NWARP - 1].x;
        cary += wpre[NWARP - 1].y;

        // ---- timestep 0: (v.x, v.y) ----
        {
            const float ax = fmaf(DT_F, ex, dv0x) - p.x;
            const float ay = fmaf(DT_F, ey, dv0y) - p.y;
            sax += ax; say += ay;
            sa2 = fmaf(ax, ax, fmaf(ay, ay, sa2));
            ex += v.x; ey += v.y;

            const float dvx = v.x - g.x, dvy = v.y - g.y;
            lve = fmaf(dvx, dvx, fmaf(dvy, dvy, lve));

            const float ivx = fminf(__expf(-c4.x), 100.0f);
            const float ivy = fminf(__expf(-c4.y), 100.0f);
            const float u   = EPS_L * ivx * ivy;
            const float logdet = fmaxf(c4.x, LN_MINVAR) + fmaxf(c4.y, LN_MINVAR)
                               + u * (1.0f - 0.5f * u);
            lcs += ivx * dvx * dvx + ivy * dvy * dvy + logdet;
            rgs += ivx + ivy;
        }
        // ---- timestep 1: (v.z, v.w) ----
        {
            const float ax = fmaf(DT_F, ex, dv0x) - p.z;
            const float ay = fmaf(DT_F, ey, dv0y) - p.w;
            sax += ax; say += ay;
            sa2 = fmaf(ax, ax, fmaf(ay, ay, sa2));

            const float dvx = v.z - g.z, dvy = v.w - g.w;
            lve = fmaf(dvx, dvx, fmaf(dvy, dvy, lve));

            const float ivx = fminf(__expf(-c4.z), 100.0f);
            const float ivy = fminf(__expf(-c4.w), 100.0f);
            const float u   = EPS_L * ivx * ivy;
            const float logdet = fmaxf(c4.z, LN_MINVAR) + fmaxf(c4.w, LN_MINVAR)
                               + u * (1.0f - 0.5f * u);
            lcs += ivx * dvx * dvx + ivy * dvy * dvy + logdet;
            rgs += ivx + ivy;
        }
    }

    // ---- block reduce 6 floats, thread 0 writes the segment record ----
    float r[6] = {sax, say, sa2, lve, lcs, rgs};
    #pragma unroll
    for (int off = 16; off > 0; off >>= 1) {
        #pragma unroll
        for (int k = 0; k < 6; ++k)
            r[k] += __shfl_down_sync(0xffffffffu, r[k], off);
    }
    if (lane == 0) {
        #pragma unroll
        for (int k = 0; k < 6; ++k) sred[wid][k] = r[k];
    }
    __syncthreads();
    if (tid == 0) {
        #pragma unroll
        for (int k = 0; k < 6; ++k) {
            float s = sred[0][k];
            #pragma unroll
            for (int w = 1; w < NWARP; ++w) s += sred[w][k];
            r[k] = s;
        }
        const int ri = q * BATCH + row;                  // [seg][row]
        g_recA[ri] = make_float4(carx, cary, r[0], r[1]); // carx/cary = segment vel sum
        g_recB[ri] = make_float4(r[2], r[3], r[4], r[5]);
    }
    // plain exit — kernel boundary orders the record stores before pass 2
}

// ================= pass 2: fp64 carry recombination (1 CTA) =================
__global__ __launch_bounds__(NTHR)
void mtl_pass2_kernel(const float*  __restrict__ log_dv_p,
                      const float*  __restrict__ log_dc_p,
                      float* __restrict__ out)
{
    __shared__ double dred[NWARP][4];

    const int tid  = threadIdx.x;
    const int lane = tid & 31;
    const int wid  = tid >> 5;

    double d[4] = {0.0, 0.0, 0.0, 0.0};
    {
        const int myrow = tid;                           // 256 threads = 256 rows
        double cxd = 0.0, cyd = 0.0;
        #pragma unroll
        for (int s = 0; s < NSEG; ++s) {
            const float4 ra = g_recA[s * BATCH + myrow]; // coalesced
            const float4 rb = g_recB[s * BATCH + myrow];
            d[0] += (double)rb.x
                  + 2.0 * DT_D * (cxd * (double)ra.z + cyd * (double)ra.w)
                  + (double)SEG * DT_D * DT_D * (cxd * cxd + cyd * cyd);
            d[1] += (double)rb.y;
            d[2] += (double)rb.z;
            d[3] += (double)rb.w;
            cxd += (double)ra.x;
            cyd += (double)ra.y;
        }
    }

    #pragma unroll
    for (int off = 16; off > 0; off >>= 1) {
        #pragma unroll
        for (int k = 0; k < 4; ++k)
            d[k] += __shfl_down_sync(0xffffffffu, d[k], off);
    }
    if (lane == 0) {
        #pragma unroll
        for (int k = 0; k < 4; ++k) dred[wid][k] = d[k];
    }
    __syncthreads();
    if (tid == 0) {
        #pragma unroll
        for (int k = 0; k < 4; ++k) {
            double s = dred[0][k];
            #pragma unroll
            for (int w = 1; w < NWARP; ++w) s += dred[w][k];
            d[k] = s;
        }
        const double n_all = (double)BATCH * (double)TLEN * 2.0;
        const double n_bt  = (double)BATCH * (double)TLEN;
        const float  ldv = *log_dv_p;
        const float  ldc = *log_dc_p;
        const double dv  = exp((double)ldv);
        const double dc  = exp((double)ldc);

        const double lv_total = (d[0] + d[1]) / n_all;
        const double lc_total = 0.5 * (d[2] / n_bt);
        const double reg      = d[3] / n_bt;

        double total = lv_total / (2.0 * dv * dv)
                     + lc_total / (2.0 * dc * dc)
                     + (double)ldv + (double)ldc
                     + REG_W * reg;
        *out = (float)total;
    }
}

extern "C" void kernel_launch(void* const* d_in, const int* in_sizes, int n_in,
                              void* d_out, int out_size)
{
    const float4* vel4 = (const float4*)d_in[0];
    const float4* cov4 = (const float4*)d_in[1];
    const float4* vgt4 = (const float4*)d_in[2];
    const float4* pgt4 = (const float4*)d_in[3];
    const float2* vel2 = (const float2*)d_in[0];
    const float*  ldv  = (const float*)d_in[4];
    const float*  ldc  = (const float*)d_in[5];
    float* out = (float*)d_out;

    mtl_pass1_kernel<<<NGRID, NTHR>>>(vel4, cov4, vgt4, pgt4, vel2);
    mtl_pass2_kernel<<<1, NTHR>>>(ldv, ldc, out);
}

// round 15
// speedup vs baseline: 1.1548x; 1.1548x over previous
#include <cuda_runtime.h>
#include <cuda_bf16.h>

#define DT_F      0.01f
#define REG_W     0.01
#define EPS_L     1e-6f
#define LN_MINVAR (-4.6051702f)   // ln(0.01)
#define BATCH     256
#define TLEN      16384
#define NTHR      256             // threads per CTA (8 warps)
#define NWARP     8
#define NCHUNK    8               // chunks per CTA
#define CHUNK_TS  (NTHR*2)        // 512 timesteps per chunk (2 ts per thread)
#define SEG       (NCHUNK*CHUNK_TS) // 4096 timesteps per CTA segment
#define NSEG      (TLEN/SEG)      // 4 segments per row
#define NGRID     (BATCH*NSEG)    // 1024 CTAs
#define NREC      (BATCH*NSEG)    // 1024 records

// Per-segment records, [seg][row] so pass-2 reads coalesced.
// recA = (sum_vel.x, sum_vel.y, sum_a.x, sum_a.y)
// recB = (sum_a2, lve, lcs, rgs)
__device__ float4 g_recA[NREC];
__device__ float4 g_recB[NREC];

// ================= pass 1: streaming workers, NO fences/atomics =================
__global__ __launch_bounds__(NTHR)
void mtl_pass1_kernel(const float4* __restrict__ vel4,
                      const float4* __restrict__ cov4,
                      const float4* __restrict__ vgt4,
                      const float4* __restrict__ pgt4,
                      const float2* __restrict__ vel2)
{
    __shared__ float2 wsum[NWARP];        // raw warp totals
    __shared__ float2 wpre[NWARP];        // inclusive-scanned warp totals
    __shared__ float  sred[NWARP][6];

    const int tid  = threadIdx.x;
    const int lane = tid & 31;
    const int wid  = tid >> 5;
    const int row  = blockIdx.x & (BATCH - 1);
    const int q    = blockIdx.x >> 8;     // segment 0..3

    const int base_f4 = (row * TLEN + q * SEG) >> 1;   // float4 index of segment start

    const float2 v0  = vel2[row * TLEN];  // broadcast
    const float dv0x = DT_F * v0.x;
    const float dv0y = DT_F * v0.y;

    float carx = 0.f, cary = 0.f;         // segment-local prefix carry
    float sax = 0.f, say = 0.f, sa2 = 0.f;
    float lve = 0.f, lcs = 0.f, rgs = 0.f;

    #pragma unroll 1
    for (int ch = 0; ch < NCHUNK; ++ch) {
        const int f4 = base_f4 + (ch * CHUNK_TS >> 1) + tid;

        const float4 v  = vel4[f4];
        const float4 c4 = cov4[f4];
        const float4 g  = vgt4[f4];
        const float4 p  = pgt4[f4];

        // ---- warp scan of per-thread (2 ts) vel sums ----
        const float tsx = v.x + v.z;
        const float tsy = v.y + v.w;
        float ix = tsx, iy = tsy;
        #pragma unroll
        for (int off = 1; off < 32; off <<= 1) {
            const float nx = __shfl_up_sync(0xffffffffu, ix, off);
            const float ny = __shfl_up_sync(0xffffffffu, iy, off);
            if (lane >= off) { ix += nx; iy += ny; }
        }
        if (lane == 31) wsum[wid] = make_float2(ix, iy);
        __syncthreads();                  // barrier 1: wsum visible

        // warp 0 lanes 0..7 scan the 8 warp totals into wpre
        if (tid < NWARP) {
            float sx = wsum[tid].x, sy = wsum[tid].y;
            #pragma unroll
            for (int off = 1; off < NWARP; off <<= 1) {
                const float nx = __shfl_up_sync(0xffu, sx, off);
                const float ny = __shfl_up_sync(0xffu, sy, off);
                if (tid >= off) { sx += nx; sy += ny; }
            }
            wpre[tid] = make_float2(sx, sy);
        }
        __syncthreads();                  // barrier 2: wpre visible

        float ex = carx + (ix - tsx);
        float ey = cary + (iy - tsy);
        if (wid > 0) { ex += wpre[wid - 1].x; ey += wpre[wid - 1].y; }
        carx += wpre[NWARP - 1].x;
        cary += wpre[NWARP - 1].y;

        // ---- timestep 0: (v.x, v.y) ----
        {
            const float ax = fmaf(DT_F, ex, dv0x) - p.x;
            const float ay = fmaf(DT_F, ey, dv0y) - p.y;
            sax += ax; say += ay;
            sa2 = fmaf(ax, ax, fmaf(ay, ay, sa2));
            ex += v.x; ey += v.y;

            const float dvx = v.x - g.x, dvy = v.y - g.y;
            lve = fmaf(dvx, dvx, fmaf(dvy, dvy, lve));

            const float ivx = fminf(__expf(-c4.x), 100.0f);
            const float ivy = fminf(__expf(-c4.y), 100.0f);
            const float u   = EPS_L * ivx * ivy;
            const float logdet = fmaxf(c4.x, LN_MINVAR) + fmaxf(c4.y, LN_MINVAR)
                               + u * (1.0f - 0.5f * u);
            lcs += ivx * dvx * dvx + ivy * dvy * dvy + logdet;
            rgs += ivx + ivy;
        }
        // ---- timestep 1: (v.z, v.w) ----
        {
            const float ax = fmaf(DT_F, ex, dv0x) - p.z;
            const float ay = fmaf(DT_F, ey, dv0y) - p.w;
            sax += ax; say += ay;
            sa2 = fmaf(ax, ax, fmaf(ay, ay, sa2));

            const float dvx = v.z - g.z, dvy = v.w - g.w;
            lve = fmaf(dvx, dvx, fmaf(dvy, dvy, lve));

            const float ivx = fminf(__expf(-c4.z), 100.0f);
            const float ivy = fminf(__expf(-c4.w), 100.0f);
            const float u   = EPS_L * ivx * ivy;
            const float logdet = fmaxf(c4.z, LN_MINVAR) + fmaxf(c4.w, LN_MINVAR)
                               + u * (1.0f - 0.5f * u);
            lcs += ivx * dvx * dvx + ivy * dvy * dvy + logdet;
            rgs += ivx + ivy;
        }
    }

    // ---- block reduce 6 floats, thread 0 writes the segment record ----
    float r[6] = {sax, say, sa2, lve, lcs, rgs};
    #pragma unroll
    for (int off = 16; off > 0; off >>= 1) {
        #pragma unroll
        for (int k = 0; k < 6; ++k)
            r[k] += __shfl_down_sync(0xffffffffu, r[k], off);
    }
    if (lane == 0) {
        #pragma unroll
        for (int k = 0; k < 6; ++k) sred[wid][k] = r[k];
    }
    __syncthreads();
    if (tid == 0) {
        #pragma unroll
        for (int k = 0; k < 6; ++k) {
            float s = sred[0][k];
            #pragma unroll
            for (int w = 1; w < NWARP; ++w) s += sred[w][k];
            r[k] = s;
        }
        const int ri = q * BATCH + row;                  // [seg][row]
        g_recA[ri] = make_float4(carx, cary, r[0], r[1]); // carx/cary = segment vel sum
        g_recB[ri] = make_float4(r[2], r[3], r[4], r[5]);
    }
    // plain exit — kernel boundary orders the record stores before pass 2
}

// ================= pass 2: fp32 carry recombination (1 CTA, fp64 only on thread 0) =================
__global__ __launch_bounds__(NTHR)
void mtl_pass2_kernel(const float*  __restrict__ log_dv_p,
                      const float*  __restrict__ log_dc_p,
                      float* __restrict__ out)
{
    __shared__ float fred[NWARP][4];

    const int tid  = threadIdx.x;
    const int lane = tid & 31;
    const int wid  = tid >> 5;

    // Per-row recombination in fp32 (magnitudes ~1e4; fp32 error << 1e-3 budget)
    float f[4] = {0.f, 0.f, 0.f, 0.f};   // lvp, lve, lcs, rgs
    {
        const int myrow = tid;            // 256 threads = 256 rows
        float cx = 0.f, cy = 0.f;         // fp32 vel carry across segments
        #pragma unroll
        for (int s = 0; s < NSEG; ++s) {
            const float4 ra = g_recA[s * BATCH + myrow];  // coalesced
            const float4 rb = g_recB[s * BATCH + myrow];
            // sum over segment of (a + DT*c)^2 for both components:
            //   sum_a2 + 2*DT*(cx*sum_ax + cy*sum_ay) + SEG*DT^2*(cx^2+cy^2)
            const float cross = cx * ra.z + cy * ra.w;
            const float csq   = cx * cx + cy * cy;
            f[0] += rb.x + 2.0f * DT_F * cross
                  + (float)SEG * (DT_F * DT_F) * csq;
            f[1] += rb.y;
            f[2] += rb.z;
            f[3] += rb.w;
            cx += ra.x;
            cy += ra.y;
        }
    }

    // fp32 tree reduce across 256 threads
    #pragma unroll
    for (int off = 16; off > 0; off >>= 1) {
        #pragma unroll
        for (int k = 0; k < 4; ++k)
            f[k] += __shfl_down_sync(0xffffffffu, f[k], off);
    }
    if (lane == 0) {
        #pragma unroll
        for (int k = 0; k < 4; ++k) fred[wid][k] = f[k];
    }
    __syncthreads();
    if (tid == 0) {
        double d[4];
        #pragma unroll
        for (int k = 0; k < 4; ++k) {
            // pairwise-ish final sum of 8 warp partials in fp64 (cheap, 8 values)
            double s = 0.0;
            #pragma unroll
            for (int w = 0; w < NWARP; ++w) s += (double)fred[w][k];
            d[k] = s;
        }
        const double n_all = (double)BATCH * (double)TLEN * 2.0;
        const double n_bt  = (double)BATCH * (double)TLEN;
        const float  ldv = *log_dv_p;
        const float  ldc = *log_dc_p;
        const double dv  = exp((double)ldv);
        const double dc  = exp((double)ldc);

        const double lv_total = (d[0] + d[1]) / n_all;
        const double lc_total = 0.5 * (d[2] / n_bt);
        const double reg      = d[3] / n_bt;

        double total = lv_total / (2.0 * dv * dv)
                     + lc_total / (2.0 * dc * dc)
                     + (double)ldv + (double)ldc
                     + REG_W * reg;
        *out = (float)total;
    }
}

extern "C" void kernel_launch(void* const* d_in, const int* in_sizes, int n_in,
                              void* d_out, int out_size)
{
    const float4* vel4 = (const float4*)d_in[0];
    const float4* cov4 = (const float4*)d_in[1];
    const float4* vgt4 = (const float4*)d_in[2];
    const float4* pgt4 = (const float4*)d_in[3];
    const float2* vel2 = (const float2*)d_in[0];
    const float*  ldv  = (const float*)d_in[4];
    const float*  ldc  = (const float*)d_in[5];
    float* out = (float*)d_out;

    mtl_pass1_kernel<<<NGRID, NTHR>>>(vel4, cov4, vgt4, pgt4, vel2);
    mtl_pass2_kernel<<<1, NTHR>>>(ldv, ldc, out);
}

// round 16
// speedup vs baseline: 1.3227x; 1.1454x over previous
#include <cuda_runtime.h>
#include <cuda_bf16.h>

#define DT_F      0.01f
#define REG_W     0.01f
#define EPS_L     1e-6f
#define LN_MINVAR (-4.6051702f)   // ln(0.01)
#define BATCH     256
#define TLEN      16384
#define NTHR      256             // threads per CTA (8 warps)
#define NWARP     8
#define NCHUNK    8               // chunks per CTA
#define CHUNK_TS  (NTHR*2)        // 512 timesteps per chunk (2 ts per thread)
#define CHUNK_F4  (CHUNK_TS/2)    // 256 float4 per chunk
#define SEG       (NCHUNK*CHUNK_TS) // 4096 timesteps per CTA segment
#define NSEG      (TLEN/SEG)      // 4 segments per row
#define NGRID     (BATCH*NSEG)    // 1024 CTAs
#define NREC      (BATCH*NSEG)    // 1024 records

// Per-segment records, [seg][row] so pass-2 reads coalesced.
// recA = (sum_vel.x, sum_vel.y, sum_a.x, sum_a.y)
// recB = (sum_a2, lve, lcs, rgs)
__device__ float4 g_recA[NREC];
__device__ float4 g_recB[NREC];

// ================= pass 1: streaming workers, NO fences/atomics =================
__global__ __launch_bounds__(NTHR)
void mtl_pass1_kernel(const float4* __restrict__ vel4,
                      const float4* __restrict__ cov4,
                      const float4* __restrict__ vgt4,
                      const float4* __restrict__ pgt4,
                      const float2* __restrict__ vel2)
{
    __shared__ float2 wsum[NWARP];        // raw warp totals
    __shared__ float2 wpre[NWARP];        // inclusive-scanned warp totals
    __shared__ float  sred[NWARP][6];

    const int tid  = threadIdx.x;
    const int lane = tid & 31;
    const int wid  = tid >> 5;
    const int row  = blockIdx.x & (BATCH - 1);
    const int q    = blockIdx.x >> 8;     // segment 0..3

    const int base_f4 = (row * TLEN + q * SEG) >> 1;   // float4 index of segment start

    const float2 v0  = vel2[row * TLEN];  // broadcast
    const float dv0x = DT_F * v0.x;
    const float dv0y = DT_F * v0.y;

    float carx = 0.f, cary = 0.f;         // segment-local prefix carry
    float sax = 0.f, say = 0.f, sa2 = 0.f;
    float lve = 0.f, lcs = 0.f, rgs = 0.f;

    // prefetch chunk 0's vel (the scan's critical operand)
    float4 v = vel4[base_f4 + tid];

    #pragma unroll 1
    for (int ch = 0; ch < NCHUNK; ++ch) {
        const int f4 = base_f4 + ch * CHUNK_F4 + tid;

        // issue this chunk's remaining loads (consumed post-scan: ~300cyc hidden)
        const float4 c4 = cov4[f4];
        const float4 g  = vgt4[f4];
        const float4 p  = pgt4[f4];
        // prefetch NEXT chunk's vel so its latency hides behind this chunk's
        // scan + barriers + compute
        float4 vn = v;
        if (ch + 1 < NCHUNK) vn = vel4[f4 + CHUNK_F4];

        // ---- warp scan of per-thread (2 ts) vel sums ----
        const float tsx = v.x + v.z;
        const float tsy = v.y + v.w;
        float ix = tsx, iy = tsy;
        #pragma unroll
        for (int off = 1; off < 32; off <<= 1) {
            const float nx = __shfl_up_sync(0xffffffffu, ix, off);
            const float ny = __shfl_up_sync(0xffffffffu, iy, off);
            if (lane >= off) { ix += nx; iy += ny; }
        }
        if (lane == 31) wsum[wid] = make_float2(ix, iy);
        __syncthreads();                  // barrier 1: wsum visible

        // warp 0 lanes 0..7 scan the 8 warp totals into wpre
        if (tid < NWARP) {
            float sx = wsum[tid].x, sy = wsum[tid].y;
            #pragma unroll
            for (int off = 1; off < NWARP; off <<= 1) {
                const float nx = __shfl_up_sync(0xffu, sx, off);
                const float ny = __shfl_up_sync(0xffu, sy, off);
                if (tid >= off) { sx += nx; sy += ny; }
            }
            wpre[tid] = make_float2(sx, sy);
        }
        __syncthreads();                  // barrier 2: wpre visible

        float ex = carx + (ix - tsx);
        float ey = cary + (iy - tsy);
        if (wid > 0) { ex += wpre[wid - 1].x; ey += wpre[wid - 1].y; }
        carx += wpre[NWARP - 1].x;
        cary += wpre[NWARP - 1].y;

        // ---- timestep 0: (v.x, v.y) ----
        {
            const float ax = fmaf(DT_F, ex, dv0x) - p.x;
            const float ay = fmaf(DT_F, ey, dv0y) - p.y;
            sax += ax; say += ay;
            sa2 = fmaf(ax, ax, fmaf(ay, ay, sa2));
            ex += v.x; ey += v.y;

            const float dvx = v.x - g.x, dvy = v.y - g.y;
            lve = fmaf(dvx, dvx, fmaf(dvy, dvy, lve));

            const float ivx = fminf(__expf(-c4.x), 100.0f);
            const float ivy = fminf(__expf(-c4.y), 100.0f);
            const float u   = EPS_L * ivx * ivy;
            const float logdet = fmaxf(c4.x, LN_MINVAR) + fmaxf(c4.y, LN_MINVAR)
                               + u * (1.0f - 0.5f * u);
            lcs += ivx * dvx * dvx + ivy * dvy * dvy + logdet;
            rgs += ivx + ivy;
        }
        // ---- timestep 1: (v.z, v.w) ----
        {
            const float ax = fmaf(DT_F, ex, dv0x) - p.z;
            const float ay = fmaf(DT_F, ey, dv0y) - p.w;
            sax += ax; say += ay;
            sa2 = fmaf(ax, ax, fmaf(ay, ay, sa2));

            const float dvx = v.z - g.z, dvy = v.w - g.w;
            lve = fmaf(dvx, dvx, fmaf(dvy, dvy, lve));

            const float ivx = fminf(__expf(-c4.z), 100.0f);
            const float ivy = fminf(__expf(-c4.w), 100.0f);
            const float u   = EPS_L * ivx * ivy;
            const float logdet = fmaxf(c4.z, LN_MINVAR) + fmaxf(c4.w, LN_MINVAR)
                               + u * (1.0f - 0.5f * u);
            lcs += ivx * dvx * dvx + ivy * dvy * dvy + logdet;
            rgs += ivx + ivy;
        }

        v = vn;                           // rotate prefetch buffer
    }

    // ---- block reduce 6 floats, thread 0 writes the segment record ----
    float r[6] = {sax, say, sa2, lve, lcs, rgs};
    #pragma unroll
    for (int off = 16; off > 0; off >>= 1) {
        #pragma unroll
        for (int k = 0; k < 6; ++k)
            r[k] += __shfl_down_sync(0xffffffffu, r[k], off);
    }
    if (lane == 0) {
        #pragma unroll
        for (int k = 0; k < 6; ++k) sred[wid][k] = r[k];
    }
    __syncthreads();
    if (tid == 0) {
        #pragma unroll
        for (int k = 0; k < 6; ++k) {
            float s = sred[0][k];
            #pragma unroll
            for (int w = 1; w < NWARP; ++w) s += sred[w][k];
            r[k] = s;
        }
        const int ri = q * BATCH + row;                  // [seg][row]
        g_recA[ri] = make_float4(carx, cary, r[0], r[1]); // carx/cary = segment vel sum
        g_recB[ri] = make_float4(r[2], r[3], r[4], r[5]);
    }
    // plain exit — kernel boundary orders the record stores before pass 2
}

// ================= pass 2: fp32 recombination + fp32 finalize =================
__global__ __launch_bounds__(NTHR)
void mtl_pass2_kernel(const float*  __restrict__ log_dv_p,
                      const float*  __restrict__ log_dc_p,
                      float* __restrict__ out)
{
    __shared__ float fred[NWARP][4];

    const int tid  = threadIdx.x;
    const int lane = tid & 31;
    const int wid  = tid >> 5;

    // ---- issue ALL 8 record loads up front (no load inside carry loop) ----
    float4 ra[NSEG], rb[NSEG];
    #pragma unroll
    for (int s = 0; s < NSEG; ++s) ra[s] = g_recA[s * BATCH + tid];
    #pragma unroll
    for (int s = 0; s < NSEG; ++s) rb[s] = g_recB[s * BATCH + tid];

    // Per-row recombination in fp32 (magnitudes ~1e4; error << 1e-3 budget)
    float f[4] = {0.f, 0.f, 0.f, 0.f};   // lvp, lve, lcs, rgs
    {
        float cx = 0.f, cy = 0.f;         // vel carry across segments
        #pragma unroll
        for (int s = 0; s < NSEG; ++s) {
            const float cross = cx * ra[s].z + cy * ra[s].w;
            const float csq   = cx * cx + cy * cy;
            f[0] += rb[s].x + 2.0f * DT_F * cross
                  + (float)SEG * (DT_F * DT_F) * csq;
            f[1] += rb[s].y;
            f[2] += rb[s].z;
            f[3] += rb[s].w;
            cx += ra[s].x;
            cy += ra[s].y;
        }
    }

    // fp32 tree reduce across 256 threads
    #pragma unroll
    for (int off = 16; off > 0; off >>= 1) {
        #pragma unroll
        for (int k = 0; k < 4; ++k)
            f[k] += __shfl_down_sync(0xffffffffu, f[k], off);
    }
    if (lane == 0) {
        #pragma unroll
        for (int k = 0; k < 4; ++k) fred[wid][k] = f[k];
    }
    __syncthreads();
    if (tid == 0) {
        #pragma unroll
        for (int k = 0; k < 4; ++k) {
            float s = fred[0][k];
            #pragma unroll
            for (int w = 1; w < NWARP; ++w) s += fred[w][k];
            f[k] = s;
        }
        const float inv_n_all = 1.0f / ((float)BATCH * (float)TLEN * 2.0f);
        const float inv_n_bt  = 1.0f / ((float)BATCH * (float)TLEN);
        const float ldv = *log_dv_p;
        const float ldc = *log_dc_p;
        // 1/(2*exp(ld)^2) = 0.5*exp(-2*ld) — no divides, no fp64
        const float inv2dv2 = 0.5f * __expf(-2.0f * ldv);
        const float inv2dc2 = 0.5f * __expf(-2.0f * ldc);

        const float lv_total = (f[0] + f[1]) * inv_n_all;
        const float lc_total = 0.5f * (f[2] * inv_n_bt);
        const float reg      = f[3] * inv_n_bt;

        *out = lv_total * inv2dv2 + lc_total * inv2dc2
             + ldv + ldc + REG_W * reg;
    }
}

extern "C" void kernel_launch(void* const* d_in, const int* in_sizes, int n_in,
                              void* d_out, int out_size)
{
    const float4* vel4 = (const float4*)d_in[0];
    const float4* cov4 = (const float4*)d_in[1];
    const float4* vgt4 = (const float4*)d_in[2];
    const float4* pgt4 = (const float4*)d_in[3];
    const float2* vel2 = (const float2*)d_in[0];
    const float*  ldv  = (const float*)d_in[4];
    const float*  ldc  = (const float*)d_in[5];
    float* out = (float*)d_out;

    mtl_pass1_kernel<<<NGRID, NTHR>>>(vel4, cov4, vgt4, pgt4, vel2);
    mtl_pass2_kernel<<<1, NTHR>>>(ldv, ldc, out);
}

// round 17
// speedup vs baseline: 1.4083x; 1.0648x over previous
#include <cuda_runtime.h>
#include <cuda_bf16.h>

#define DT_F      0.01f
#define REG_W     0.01f
#define EPS_L     1e-6f
#define LN_MINVAR (-4.6051702f)   // ln(0.01)
#define BATCH     256
#define TLEN      16384
#define NTHR      256             // threads per CTA (8 warps)
#define NWARP     8
#define STRIPE    512             // timesteps per warp stripe
#define NRND      8               // rounds per stripe (64 ts per round)
#define SEG       (NWARP*STRIPE)  // 4096 timesteps per CTA segment
#define NSEG      (TLEN/SEG)      // 4 segments per row
#define NGRID     (BATCH*NSEG)    // 1024 CTAs
#define NREC      (BATCH*NSEG)    // 1024 records

// Per-segment records, [seg][row] so pass-2 reads coalesced.
// recA = (sum_vel.x, sum_vel.y, sum_a.x, sum_a.y)
// recB = (sum_a2, lve, lcs, rgs)
__device__ float4 g_recA[NREC];
__device__ float4 g_recB[NREC];

// ================= pass 1: barrier-free warp stripes, two-pass protocol =================
__global__ __launch_bounds__(NTHR)
void mtl_pass1_kernel(const float4* __restrict__ vel4,
                      const float4* __restrict__ cov4,
                      const float4* __restrict__ vgt4,
                      const float4* __restrict__ pgt4,
                      const float2* __restrict__ vel2)
{
    // per-warp stripe results: [svx, svy, sax~, say~, sa2~, lve, lcs, rgs]
    __shared__ float sdat[NWARP][8];

    const int tid  = threadIdx.x;
    const int lane = tid & 31;
    const int wid  = tid >> 5;
    const int row  = blockIdx.x & (BATCH - 1);
    const int q    = blockIdx.x >> 8;     // segment 0..3

    // float4 index of this lane's first ts-pair in round 0 of its stripe
    int f4 = ((row * TLEN + q * SEG + wid * STRIPE) >> 1) + lane;

    const float2 v0  = vel2[row * TLEN];  // broadcast
    const float dv0x = DT_F * v0.x;
    const float dv0y = DT_F * v0.y;

    // ---- prefetch round 0 (all 4 arrays) ----
    float4 nv = vel4[f4];
    float4 nc = cov4[f4];
    float4 ng = vgt4[f4];
    float4 np = pgt4[f4];

    float carx = 0.f, cary = 0.f;         // stripe-local prefix carry (uniform in warp)
    float sax = 0.f, say = 0.f, sa2 = 0.f;
    float lve = 0.f, lcs = 0.f, rgs = 0.f;

    #pragma unroll 1
    for (int r = 0; r < NRND; ++r) {
        const float4 v = nv, c4 = nc, g = ng, p = np;

        // issue next round's loads FIRST (hidden behind scan + compute)
        f4 += 32;
        if (r + 1 < NRND) {
            nv = vel4[f4];
            nc = cov4[f4];
            ng = vgt4[f4];
            np = pgt4[f4];
        }

        // ---- warp-local scan of per-lane (2 ts) vel sums — no barriers ----
        const float tsx = v.x + v.z;
        const float tsy = v.y + v.w;
        float ix = tsx, iy = tsy;
        #pragma unroll
        for (int off = 1; off < 32; off <<= 1) {
            const float nx = __shfl_up_sync(0xffffffffu, ix, off);
            const float ny = __shfl_up_sync(0xffffffffu, iy, off);
            if (lane >= off) { ix += nx; iy += ny; }
        }
        float ex = carx + (ix - tsx);     // stripe-local exclusive prefix, ts0
        float ey = cary + (iy - tsy);
        carx += __shfl_sync(0xffffffffu, ix, 31);   // round total -> carry
        cary += __shfl_sync(0xffffffffu, iy, 31);

        // ---- timestep 0: (v.x, v.y) ----
        {
            const float ax = fmaf(DT_F, ex, dv0x) - p.x;
            const float ay = fmaf(DT_F, ey, dv0y) - p.y;
            sax += ax; say += ay;
            sa2 = fmaf(ax, ax, fmaf(ay, ay, sa2));
            ex += v.x; ey += v.y;

            const float dvx = v.x - g.x, dvy = v.y - g.y;
            lve = fmaf(dvx, dvx, fmaf(dvy, dvy, lve));

            const float ivx = fminf(__expf(-c4.x), 100.0f);
            const float ivy = fminf(__expf(-c4.y), 100.0f);
            const float u   = EPS_L * ivx * ivy;
            const float logdet = fmaxf(c4.x, LN_MINVAR) + fmaxf(c4.y, LN_MINVAR)
                               + u * (1.0f - 0.5f * u);
            lcs += ivx * dvx * dvx + ivy * dvy * dvy + logdet;
            rgs += ivx + ivy;
        }
        // ---- timestep 1: (v.z, v.w) ----
        {
            const float ax = fmaf(DT_F, ex, dv0x) - p.z;
            const float ay = fmaf(DT_F, ey, dv0y) - p.w;
            sax += ax; say += ay;
            sa2 = fmaf(ax, ax, fmaf(ay, ay, sa2));

            const float dvx = v.z - g.z, dvy = v.w - g.w;
            lve = fmaf(dvx, dvx, fmaf(dvy, dvy, lve));

            const float ivx = fminf(__expf(-c4.z), 100.0f);
            const float ivy = fminf(__expf(-c4.w), 100.0f);
            const float u   = EPS_L * ivx * ivy;
            const float logdet = fmaxf(c4.z, LN_MINVAR) + fmaxf(c4.w, LN_MINVAR)
                               + u * (1.0f - 0.5f * u);
            lcs += ivx * dvx * dvx + ivy * dvy * dvy + logdet;
            rgs += ivx + ivy;
        }
    }

    // ---- warp reduce the 6 lane-distributed sums (carx/cary already uniform) ----
    float rr[6] = {sax, say, sa2, lve, lcs, rgs};
    #pragma unroll
    for (int off = 16; off > 0; off >>= 1) {
        #pragma unroll
        for (int k = 0; k < 6; ++k)
            rr[k] += __shfl_down_sync(0xffffffffu, rr[k], off);
    }
    if (lane == 0) {
        sdat[wid][0] = carx;    // stripe vel sum x
        sdat[wid][1] = cary;    // stripe vel sum y
        sdat[wid][2] = rr[0];   // sum_a~ x (stripe-local prefix)
        sdat[wid][3] = rr[1];   // sum_a~ y
        sdat[wid][4] = rr[2];   // sum_a2~
        sdat[wid][5] = rr[3];   // lve
        sdat[wid][6] = rr[4];   // lcs
        sdat[wid][7] = rr[5];   // rgs
    }
    __syncthreads();            // the ONLY block barrier

    // ---- epilogue: thread 0 recombines the 8 stripes into one segment record ----
    if (tid == 0) {
        const float n    = (float)STRIPE;
        const float ndt2 = n * DT_F * DT_F;
        float Cx = 0.f, Cy = 0.f;                 // vel carry across stripes
        float svax = 0.f, svay = 0.f, sva2 = 0.f;
        float lveS = 0.f, lcsS = 0.f, rgsS = 0.f;
        #pragma unroll
        for (int w = 0; w < NWARP; ++w) {
            const float svx = sdat[w][0], svy = sdat[w][1];
            const float ax_ = sdat[w][2], ay_ = sdat[w][3];
            const float a2_ = sdat[w][4];
            sva2 += a2_ + 2.0f * DT_F * (Cx * ax_ + Cy * ay_)
                  + ndt2 * (Cx * Cx + Cy * Cy);
            svax += ax_ + n * DT_F * Cx;
            svay += ay_ + n * DT_F * Cy;
            lveS += sdat[w][5];
            lcsS += sdat[w][6];
            rgsS += sdat[w][7];
            Cx += svx;
            Cy += svy;
        }
        const int ri = q * BATCH + row;           // [seg][row]
        g_recA[ri] = make_float4(Cx, Cy, svax, svay);   // Cx/Cy = segment vel sum
        g_recB[ri] = make_float4(sva2, lveS, lcsS, rgsS);
    }
    // plain exit — kernel boundary orders the record stores before pass 2
}

// ================= pass 2: fp32 recombination + fp32 finalize (unchanged) =================
__global__ __launch_bounds__(NTHR)
void mtl_pass2_kernel(const float*  __restrict__ log_dv_p,
                      const float*  __restrict__ log_dc_p,
                      float* __restrict__ out)
{
    __shared__ float fred[NWARP][4];

    const int tid  = threadIdx.x;
    const int lane = tid & 31;
    const int wid  = tid >> 5;

    // ---- issue ALL 8 record loads up front ----
    float4 ra[NSEG], rb[NSEG];
    #pragma unroll
    for (int s = 0; s < NSEG; ++s) ra[s] = g_recA[s * BATCH + tid];
    #pragma unroll
    for (int s = 0; s < NSEG; ++s) rb[s] = g_recB[s * BATCH + tid];

    float f[4] = {0.f, 0.f, 0.f, 0.f};   // lvp, lve, lcs, rgs
    {
        float cx = 0.f, cy = 0.f;
        #pragma unroll
        for (int s = 0; s < NSEG; ++s) {
            const float cross = cx * ra[s].z + cy * ra[s].w;
            const float csq   = cx * cx + cy * cy;
            f[0] += rb[s].x + 2.0f * DT_F * cross
                  + (float)SEG * (DT_F * DT_F) * csq;
            f[1] += rb[s].y;
            f[2] += rb[s].z;
            f[3] += rb[s].w;
            cx += ra[s].x;
            cy += ra[s].y;
        }
    }

    #pragma unroll
    for (int off = 16; off > 0; off >>= 1) {
        #pragma unroll
        for (int k = 0; k < 4; ++k)
            f[k] += __shfl_down_sync(0xffffffffu, f[k], off);
    }
    if (lane == 0) {
        #pragma unroll
        for (int k = 0; k < 4; ++k) fred[wid][k] = f[k];
    }
    __syncthreads();
    if (tid == 0) {
        #pragma unroll
        for (int k = 0; k < 4; ++k) {
            float s = fred[0][k];
            #pragma unroll
            for (int w = 1; w < NWARP; ++w) s += fred[w][k];
            f[k] = s;
        }
        const float inv_n_all = 1.0f / ((float)BATCH * (float)TLEN * 2.0f);
        const float inv_n_bt  = 1.0f / ((float)BATCH * (float)TLEN);
        const float ldv = *log_dv_p;
        const float ldc = *log_dc_p;
        const float inv2dv2 = 0.5f * __expf(-2.0f * ldv);
        const float inv2dc2 = 0.5f * __expf(-2.0f * ldc);

        const float lv_total = (f[0] + f[1]) * inv_n_all;
        const float lc_total = 0.5f * (f[2] * inv_n_bt);
        const float reg      = f[3] * inv_n_bt;

        *out = lv_total * inv2dv2 + lc_total * inv2dc2
             + ldv + ldc + REG_W * reg;
    }
}

extern "C" void kernel_launch(void* const* d_in, const int* in_sizes, int n_in,
                              void* d_out, int out_size)
{
    const float4* vel4 = (const float4*)d_in[0];
    const float4* cov4 = (const float4*)d_in[1];
    const float4* vgt4 = (const float4*)d_in[2];
    const float4* pgt4 = (const float4*)d_in[3];
    const float2* vel2 = (const float2*)d_in[0];
    const float*  ldv  = (const float*)d_in[4];
    const float*  ldc  = (const float*)d_in[5];
    float* out = (float*)d_out;

    mtl_pass1_kernel<<<NGRID, NTHR>>>(vel4, cov4, vgt4, pgt4, vel2);
    mtl_pass2_kernel<<<1, NTHR>>>(ldv, ldc, out);
}